// round 9
// baseline (speedup 1.0000x reference)
#include <cuda_runtime.h>
#include <cuda_fp16.h>
#include <cstdint>
#include <cstddef>

#define D_IN 512
#define DH   32
#define NC   40
#define MAXN 100000
#define MAXE 3200000
#define MAXE2 4000000            // padded CSR capacity: E + 8*N
#define SCAN_CHUNK 1024
#define MAXBLKS 128
#define BM 256
#define BK 16

// padded smem geometry (conflict-free)
#define XS_G   12
#define XS_ROW (32 * XS_G)
#define WS_T   10
#define WS_ROW (4 * WS_T)

typedef unsigned long long ull;

// ---------------- device scratch (referenced only from device code) ----------------
__device__ __align__(128) int    g_deg[MAXN];
__device__ __align__(128) int    g_rp[MAXN + 1];
__device__ __align__(128) int    g_cursor[MAXN];
__device__ __align__(128) float  g_dinv[MAXN];
__device__ __align__(128) int    g_csr[MAXE2];
__device__ __align__(128) int    g_es[MAXE];
__device__ __align__(128) int    g_ed[MAXE];
__device__ __align__(128) __half g_hA[(size_t)(MAXN + 1) * DH];  // +1: zero row for pads
__device__ __align__(128) float  g_bufB[(size_t)MAXN * DH];
__device__ __align__(128) __half g_hgf[(size_t)(MAXN + 1) * NC]; // +1: zero row for pads
__device__ volatile ull g_lk[MAXBLKS];   // decoupled-lookback: (sum<<2)|flag
__device__ float g_statsA[DH + 1];
__device__ float g_statsB[DH + 1];
__device__ int   g_is64;

// ---------------- helpers ----------------
__device__ __forceinline__ void ffma2(ull& d, ull a, ull b) {
    asm("fma.rn.f32x2 %0, %1, %2, %0;" : "+l"(d) : "l"(a), "l"(b));
}
__device__ __forceinline__ ull splat2(float v) {
    unsigned u = __float_as_uint(v);
    ull r;
    asm("mov.b64 %0, {%1,%1};" : "=l"(r) : "r"(u));
    return r;
}
__device__ __forceinline__ float4 h4_to_f4(uint2 u) {
    __half2 h0 = *reinterpret_cast<__half2*>(&u.x);
    __half2 h1 = *reinterpret_cast<__half2*>(&u.y);
    float2 f0 = __half22float2(h0);
    float2 f1 = __half22float2(h1);
    return make_float4(f0.x, f0.y, f1.x, f1.y);
}

// ---------------- init: csr=N fill, deg=0, stats, lookback flags, detect dtype --------
__global__ void k_init(const int* __restrict__ p, int N) {
    int i = blockIdx.x * blockDim.x + threadIdx.x;
    if (i < (MAXE2 >> 2)) {
        *(int4*)(g_csr + i * 4) = make_int4(N, N, N, N);
    }
    if (i < N) g_deg[i] = 0;
    if (blockIdx.x == 0) {
        int tid = threadIdx.x;
        if (tid < DH + 1) g_statsA[tid] = 0.f;
        if (tid < MAXBLKS) g_lk[tid] = 0ull;
        if (tid < DH) g_hA[(size_t)N * DH + tid] = __float2half(0.f);
        if (tid < NC) g_hgf[(size_t)N * NC + tid] = __float2half(0.f);
        if (tid < 32) {
            int v = p[2 * tid + 1];
            unsigned any = __ballot_sync(0xffffffffu, v != 0);
            if (tid == 0) g_is64 = (any == 0) ? 1 : 0;
        }
    }
}

// ---------------- count degrees + cache int32 edges (2 edges/thread) ----------------
__global__ void k_count(const void* __restrict__ ei, int E) {
    int idx = blockIdx.x * blockDim.x + threadIdx.x;
    int e = idx * 2;
    if (e >= E) return;
    int s0, s1 = 0, d0, d1 = 0;
    bool pair = (e + 1 < E);
    if (g_is64) {
        const long long* ps = (const long long*)ei;
        const long long* pd = ps + E;
        if ((E & 1) == 0) {
            longlong2 sv = *(const longlong2*)(ps + e);
            longlong2 dv = *(const longlong2*)(pd + e);
            s0 = (int)sv.x; s1 = (int)sv.y;
            d0 = (int)dv.x; d1 = (int)dv.y;
        } else {
            s0 = (int)ps[e]; d0 = (int)pd[e];
            if (pair) { s1 = (int)ps[e + 1]; d1 = (int)pd[e + 1]; }
        }
    } else {
        const int* ps = (const int*)ei;
        const int* pd = ps + E;
        if ((E & 1) == 0) {
            int2 sv = *(const int2*)(ps + e);
            int2 dv = *(const int2*)(pd + e);
            s0 = sv.x; s1 = sv.y;
            d0 = dv.x; d1 = dv.y;
        } else {
            s0 = ps[e]; d0 = pd[e];
            if (pair) { s1 = ps[e + 1]; d1 = pd[e + 1]; }
        }
    }
    g_es[e] = s0; g_ed[e] = d0;
    atomicAdd(&g_deg[d0], 1);
    if (pair) {
        g_es[e + 1] = s1; g_ed[e + 1] = d1;
        atomicAdd(&g_deg[d1], 1);
    }
}

// ---------------- fused scan (decoupled lookback): rp/cursor on PADDED degrees --------
__global__ void k_scan(int N) {
    __shared__ int sm[256];
    __shared__ int s_pref;
    int blk = blockIdx.x, tid = threadIdx.x;
    int base = blk * SCAN_CHUNK + tid * 4;
    int d[4], pd[4];
    int s = 0;
#pragma unroll
    for (int j = 0; j < 4; j++) {
        int i = base + j;
        d[j] = (i < N) ? g_deg[i] : 0;
        pd[j] = (d[j] + 7) & ~7;          // pad each row to multiple of 8
        s += pd[j];
    }
    sm[tid] = s;
    __syncthreads();
    int own = s;
    for (int off = 1; off < 256; off <<= 1) {
        int add = (tid >= off) ? sm[tid - off] : 0;
        __syncthreads();
        sm[tid] += add;
        __syncthreads();
    }
    int incl = sm[tid];
    int total = sm[255];

    if (tid == 0) {
        if (blk == 0) {
            g_lk[0] = ((ull)(unsigned)total << 2) | 2ull;
            s_pref = 0;
        } else {
            g_lk[blk] = ((ull)(unsigned)total << 2) | 1ull;
            int run = 0;
            int pb = blk - 1;
            while (true) {
                ull w;
                do { w = g_lk[pb]; } while ((w & 3ull) == 0ull);
                run += (int)(w >> 2);
                if ((w & 3ull) == 2ull) break;
                pb--;
            }
            s_pref = run;
            g_lk[blk] = ((ull)(unsigned)(run + total) << 2) | 2ull;
        }
    }
    __syncthreads();

    int excl = incl - own + s_pref;
#pragma unroll
    for (int j = 0; j < 4; j++) {
        int i = base + j;
        if (i < N) {
            g_rp[i] = excl;
            g_cursor[i] = excl;
            g_dinv[i] = rsqrtf((float)(d[j] + 1));
            if (i == N - 1) g_rp[N] = excl + pd[j];
            excl += pd[j];
        }
    }
}

// ---------------- fill real edges (pads remain = N from k_init) ----------------
__global__ void k_fill(int E) {
    int e = blockIdx.x * blockDim.x + threadIdx.x;
    if (e < E) {
        int dst = g_ed[e];
        int pos = atomicAdd(&g_cursor[dst], 1);
        g_csr[pos] = g_es[e];
    }
}

// ---------------- layer-0 GEMM: g_hA = fp16( dinv ⊙ (x @ W0) ) ----------------
__global__ void __launch_bounds__(128) k_gemm0(const float* __restrict__ x,
                                               const float* __restrict__ W, int N) {
    __shared__ float xs[BK * XS_ROW];
    __shared__ ull   ws2[BK * WS_ROW];
    int tid = threadIdx.x;
    int ty = tid >> 2;
    int tx = tid & 3;
    int rowBase = blockIdx.x * BM;

    if (blockIdx.x == 0 && tid < DH + 1) g_statsB[tid] = 0.f;

    ull acc2[4][8];
#pragma unroll
    for (int ip = 0; ip < 4; ip++)
#pragma unroll
        for (int j = 0; j < 8; j++) acc2[ip][j] = 0ull;

    float4 pre[8];
#pragma unroll
    for (int i = 0; i < 8; i++) {
        int idx = tid + i * 128;
        int row = idx >> 2;
        int kq = (idx & 3) << 2;
        int gr = rowBase + row;
        pre[i] = (gr < N) ? *(const float4*)(x + (size_t)gr * D_IN + kq)
                          : make_float4(0.f, 0.f, 0.f, 0.f);
    }

    for (int k0 = 0; k0 < D_IN; k0 += BK) {
#pragma unroll
        for (int i = 0; i < 8; i++) {
            int idx = tid + i * 128;
            int row = idx >> 2;
            int kq = (idx & 3) << 2;
            int base = (row >> 3) * XS_G + (row & 7);
            xs[(kq + 0) * XS_ROW + base] = pre[i].x;
            xs[(kq + 1) * XS_ROW + base] = pre[i].y;
            xs[(kq + 2) * XS_ROW + base] = pre[i].z;
            xs[(kq + 3) * XS_ROW + base] = pre[i].w;
        }
        {
            int kk = tid >> 3;
            int nq = (tid & 7) << 2;
            float4 wv = *(const float4*)(W + (size_t)(k0 + kk) * DH + nq);
            int pbase = kk * WS_ROW + (nq >> 3) * WS_T + (nq & 7);
            ws2[pbase + 0] = splat2(wv.x);
            ws2[pbase + 1] = splat2(wv.y);
            ws2[pbase + 2] = splat2(wv.z);
            ws2[pbase + 3] = splat2(wv.w);
        }
        __syncthreads();

        if (k0 + BK < D_IN) {
#pragma unroll
            for (int i = 0; i < 8; i++) {
                int idx = tid + i * 128;
                int row = idx >> 2;
                int kq = (idx & 3) << 2;
                int gr = rowBase + row;
                pre[i] = (gr < N) ? *(const float4*)(x + (size_t)gr * D_IN + k0 + BK + kq)
                                  : make_float4(0.f, 0.f, 0.f, 0.f);
            }
        }

#pragma unroll
        for (int kk = 0; kk < BK; kk++) {
            const ull* ar = (const ull*)(xs + kk * XS_ROW + ty * XS_G);
            ull ap0 = ar[0], ap1 = ar[1], ap2 = ar[2], ap3 = ar[3];
            const ull* wr = ws2 + kk * WS_ROW + tx * WS_T;
#pragma unroll
            for (int j = 0; j < 8; j++) {
                ull bs = wr[j];
                ffma2(acc2[0][j], ap0, bs);
                ffma2(acc2[1][j], ap1, bs);
                ffma2(acc2[2][j], ap2, bs);
                ffma2(acc2[3][j], ap3, bs);
            }
        }
        __syncthreads();
    }

#pragma unroll
    for (int ip = 0; ip < 4; ip++) {
        int r0 = rowBase + ty * 8 + 2 * ip;
        int r1 = r0 + 1;
        float dv0 = (r0 < N) ? g_dinv[r0] : 0.f;
        float dv1 = (r1 < N) ? g_dinv[r1] : 0.f;
        float v0[8], v1[8];
#pragma unroll
        for (int j = 0; j < 8; j++) {
            ull v = acc2[ip][j];
            v0[j] = __uint_as_float((unsigned)v) * dv0;
            v1[j] = __uint_as_float((unsigned)(v >> 32)) * dv1;
        }
#pragma unroll
        for (int j2 = 0; j2 < 4; j2++) {
            if (r0 < N)
                *(__half2*)(g_hA + (size_t)r0 * DH + tx * 8 + 2 * j2) =
                    __floats2half2_rn(v0[2 * j2], v0[2 * j2 + 1]);
            if (r1 < N)
                *(__half2*)(g_hA + (size_t)r1 * DH + tx * 8 + 2 * j2) =
                    __floats2half2_rn(v1[2 * j2], v1[2 * j2 + 1]);
        }
    }
}

// ---- propagation D=32, padded rows, unconditional gathers + fused stats ----
__global__ void k_prop32(const float* __restrict__ b, int N, int which) {
    __shared__ float s_cs[DH];
    __shared__ float s_ss;
    int tid = threadIdx.x;
    if (tid < DH) s_cs[tid] = 0.f;
    if (tid == DH) s_ss = 0.f;
    __syncthreads();

    int lane = tid & 31;
    int l8 = lane & 7;
    int g8 = lane >> 3;
    int gwarp = (blockIdx.x * blockDim.x + tid) >> 5;
    int w = gwarp * 4 + g8;
    bool alive = (w < N);
    int wc = alive ? w : 0;

    float4 acc = h4_to_f4(*((const uint2*)(g_hA + (size_t)wc * DH) + l8));  // self loop
    int beg = g_rp[wc];
    int pdg = g_rp[wc + 1] - beg;     // padded degree (multiple of 8)
    if (!alive) pdg = 0;

    int mx = pdg;
    mx = max(mx, __shfl_xor_sync(0xffffffffu, mx, 16));
    mx = max(mx, __shfl_xor_sync(0xffffffffu, mx, 8));

    for (int t0 = 0; t0 < mx; t0 += 8) {
        int s = (t0 + l8 < pdg) ? g_csr[beg + t0 + l8] : N;   // N -> zero row
#pragma unroll
        for (int k = 0; k < 8; k++) {
            int sk = __shfl_sync(0xffffffffu, s, k, 8);
            float4 v = h4_to_f4(*((const uint2*)(g_hA + (size_t)sk * DH) + l8));
            acc.x += v.x; acc.y += v.y; acc.z += v.z; acc.w += v.w;
        }
    }

    float4 o = make_float4(0.f, 0.f, 0.f, 0.f);
    if (alive) {
        float dv = g_dinv[w];
        float4 bb = *(const float4*)(b + l8 * 4);
        o.x = dv * acc.x + bb.x;
        o.y = dv * acc.y + bb.y;
        o.z = dv * acc.z + bb.z;
        o.w = dv * acc.w + bb.w;
        *(float4*)(g_bufB + (size_t)w * DH + l8 * 4) = o;
    }

    float ssl = o.x * o.x + o.y * o.y + o.z * o.z + o.w * o.w;
#pragma unroll
    for (int off = 16; off; off >>= 1) ssl += __shfl_xor_sync(0xffffffffu, ssl, off);

    o.x += __shfl_xor_sync(0xffffffffu, o.x, 8);
    o.y += __shfl_xor_sync(0xffffffffu, o.y, 8);
    o.z += __shfl_xor_sync(0xffffffffu, o.z, 8);
    o.w += __shfl_xor_sync(0xffffffffu, o.w, 8);
    o.x += __shfl_xor_sync(0xffffffffu, o.x, 16);
    o.y += __shfl_xor_sync(0xffffffffu, o.y, 16);
    o.z += __shfl_xor_sync(0xffffffffu, o.z, 16);
    o.w += __shfl_xor_sync(0xffffffffu, o.w, 16);
    if (lane < 8) {
        atomicAdd(&s_cs[l8 * 4 + 0], o.x);
        atomicAdd(&s_cs[l8 * 4 + 1], o.y);
        atomicAdd(&s_cs[l8 * 4 + 2], o.z);
        atomicAdd(&s_cs[l8 * 4 + 3], o.w);
    }
    if (lane == 0) atomicAdd(&s_ss, ssl);
    __syncthreads();

    float* st = which ? g_statsB : g_statsA;
    if (tid < DH) atomicAdd(&st[tid], s_cs[tid]);
    if (tid == DH) atomicAdd(&st[DH], s_ss);
}

// ---- fused pairnorm + relu + (t @ W1) + dinv scale: bufB -> g_hA (stats A) ----
__global__ void k_transform(const float* __restrict__ Wmat, int N, float invN) {
    __shared__ float ws[DH * DH];
    int tid = threadIdx.x, lane = tid & 31;
    for (int i = tid; i < DH * DH; i += blockDim.x) ws[i] = Wmat[i];
    __syncthreads();

    float mu = g_statsA[lane] * invN;
    float m2 = mu * mu;
#pragma unroll
    for (int off = 16; off; off >>= 1) m2 += __shfl_xor_sync(0xffffffffu, m2, off);
    float scale = rsqrtf(1e-5f + g_statsA[DH] * invN - m2);

    int warp0 = (blockIdx.x * blockDim.x + tid) >> 5;
    int nw = (gridDim.x * blockDim.x) >> 5;
    for (int n = warp0; n < N; n += nw) {
        float t = (g_bufB[(size_t)n * DH + lane] - mu) * scale;
        t = fmaxf(t, 0.f);
        float acc = 0.f;
#pragma unroll
        for (int j = 0; j < DH; j++) {
            float tj = __shfl_sync(0xffffffffu, t, j);
            acc = fmaf(tj, ws[j * DH + lane], acc);
        }
        float val = acc * g_dinv[n];
        float vhi = __shfl_down_sync(0xffffffffu, val, 1);
        if ((lane & 1) == 0)
            *(__half2*)(g_hA + (size_t)n * DH + lane) = __floats2half2_rn(val, vhi);
    }
}

// ---- fused pairnorm + relu + (t @ Wf) + dinv scale: bufB -> g_hgf (stats B) ----
__global__ void k_transformF(const float* __restrict__ Wmat, int N, float invN) {
    __shared__ float ws[DH * NC];
    int tid = threadIdx.x, lane = tid & 31;
    for (int i = tid; i < DH * NC; i += blockDim.x) ws[i] = Wmat[i];
    __syncthreads();

    float mu = g_statsB[lane] * invN;
    float m2 = mu * mu;
#pragma unroll
    for (int off = 16; off; off >>= 1) m2 += __shfl_xor_sync(0xffffffffu, m2, off);
    float scale = rsqrtf(1e-5f + g_statsB[DH] * invN - m2);

    int warp0 = (blockIdx.x * blockDim.x + tid) >> 5;
    int nw = (gridDim.x * blockDim.x) >> 5;
    int l8 = lane & 7;
    for (int n = warp0; n < N; n += nw) {
        float t = (g_bufB[(size_t)n * DH + lane] - mu) * scale;
        t = fmaxf(t, 0.f);
        float acc0 = 0.f, acc1 = 0.f;
#pragma unroll
        for (int j = 0; j < DH; j++) {
            float tj = __shfl_sync(0xffffffffu, t, j);
            acc0 = fmaf(tj, ws[j * NC + lane], acc0);
            acc1 = fmaf(tj, ws[j * NC + 32 + l8], acc1);
        }
        float dv = g_dinv[n];
        float v0 = acc0 * dv;
        float v0hi = __shfl_down_sync(0xffffffffu, v0, 1);
        if ((lane & 1) == 0)
            *(__half2*)(g_hgf + (size_t)n * NC + lane) = __floats2half2_rn(v0, v0hi);
        float v1 = acc1 * dv;
        float v1hi = __shfl_down_sync(0xffffffffu, v1, 1);
        if (lane < 8 && (lane & 1) == 0)
            *(__half2*)(g_hgf + (size_t)n * NC + 32 + lane) = __floats2half2_rn(v1, v1hi);
    }
}

// ---------------- final propagation D=40, padded rows -> d_out ----------------
__global__ void k_propF(const float* __restrict__ bf, float* __restrict__ out, int N) {
    int tid = threadIdx.x;
    int lane = tid & 31;
    int l8 = lane & 7;
    int g8 = lane >> 3;
    int gwarp = (blockIdx.x * blockDim.x + tid) >> 5;
    int w = gwarp * 4 + g8;
    bool alive = (w < N);
    int wc = alive ? w : 0;

    const __half* srow = g_hgf + (size_t)wc * NC;
    float4 acc = h4_to_f4(*((const uint2*)srow + l8));
    float2 acc1 = make_float2(0.f, 0.f);
    if (l8 < 4) {
        unsigned u = *(const unsigned*)(srow + 32 + l8 * 2);
        acc1 = __half22float2(*reinterpret_cast<__half2*>(&u));
    }
    int beg = g_rp[wc];
    int pdg = g_rp[wc + 1] - beg;
    if (!alive) pdg = 0;

    int mx = pdg;
    mx = max(mx, __shfl_xor_sync(0xffffffffu, mx, 16));
    mx = max(mx, __shfl_xor_sync(0xffffffffu, mx, 8));

    for (int t0 = 0; t0 < mx; t0 += 8) {
        int s = (t0 + l8 < pdg) ? g_csr[beg + t0 + l8] : N;
#pragma unroll
        for (int k = 0; k < 8; k++) {
            int sk = __shfl_sync(0xffffffffu, s, k, 8);
            const __half* row = g_hgf + (size_t)sk * NC;
            float4 v = h4_to_f4(*((const uint2*)row + l8));
            acc.x += v.x; acc.y += v.y; acc.z += v.z; acc.w += v.w;
            if (l8 < 4) {
                unsigned u = *(const unsigned*)(row + 32 + l8 * 2);
                float2 v1 = __half22float2(*reinterpret_cast<__half2*>(&u));
                acc1.x += v1.x; acc1.y += v1.y;
            }
        }
    }
    if (alive) {
        float dv = g_dinv[w];
        float4 bb = *(const float4*)(bf + l8 * 4);
        float4 o;
        o.x = dv * acc.x + bb.x;
        o.y = dv * acc.y + bb.y;
        o.z = dv * acc.z + bb.z;
        o.w = dv * acc.w + bb.w;
        *(float4*)(out + (size_t)w * NC + l8 * 4) = o;
        if (l8 < 4) {
            float2 be = *(const float2*)(bf + 32 + l8 * 2);
            float2 o1;
            o1.x = dv * acc1.x + be.x;
            o1.y = dv * acc1.y + be.y;
            *(float2*)(out + (size_t)w * NC + 32 + l8 * 2) = o1;
        }
    }
}

// ---------------- host launcher ----------------
extern "C" void kernel_launch(void* const* d_in, const int* in_sizes, int n_in,
                              void* d_out, int out_size) {
    const float* x  = (const float*)d_in[0];
    const void*  ei = d_in[1];
    const float* W0 = (const float*)d_in[2];
    const float* b0 = (const float*)d_in[3];
    const float* W1 = (const float*)d_in[4];
    const float* b1 = (const float*)d_in[5];
    const float* Wf = (const float*)d_in[6];
    const float* bf = (const float*)d_in[7];
    float* out = (float*)d_out;

    int N = in_sizes[0] / D_IN;
    int E = in_sizes[1] / 2;
    float invN = 1.f / (float)N;
    int NB = (N + SCAN_CHUNK - 1) / SCAN_CHUNK;
    int propBlocks = (N + 31) / 32;

    int initThreads = MAXE2 / 4;                   // 1,000,000 (covers csr int4 + deg)
    k_init<<<(initThreads + 255) / 256, 256>>>((const int*)ei, N);       // #1
    k_count<<<(E / 2 + 256) / 256, 256>>>(ei, E);                        // #2
    k_scan<<<NB, 256>>>(N);                                              // #3
    k_fill<<<(E + 255) / 256, 256>>>(E);                                 // #4 (profiled)

    k_gemm0<<<(N + BM - 1) / BM, 128>>>(x, W0, N);                       // #5
    k_prop32<<<propBlocks, 256>>>(b0, N, 0);                             // #6
    k_transform<<<592, 256>>>(W1, N, invN);                              // #7
    k_prop32<<<propBlocks, 256>>>(b1, N, 1);                             // #8
    k_transformF<<<592, 256>>>(Wf, N, invN);                             // #9
    k_propF<<<propBlocks, 256>>>(bf, out, N);                            // #10
}

// round 10
// speedup vs baseline: 1.0250x; 1.0250x over previous
#include <cuda_runtime.h>
#include <cuda_fp16.h>
#include <cstdint>
#include <cstddef>

#define D_IN 512
#define DH   32
#define NC   40
#define MAXN 100000
#define MAXE 3200000
#define SCAN_CHUNK 1024
#define MAXBLKS 128
#define BM 256
#define BK 16

// padded smem geometry (conflict-free)
#define XS_G   12
#define XS_ROW (32 * XS_G)
#define WS_T   10
#define WS_ROW (4 * WS_T)

typedef unsigned long long ull;

// ---------------- device scratch (referenced only from device code) ----------------
__device__ __align__(128) int    g_deg[MAXN];
__device__ __align__(128) int    g_rp[MAXN + 1];
__device__ __align__(128) float  g_dinv[MAXN];
__device__ __align__(128) int    g_csr[MAXE];
__device__ __align__(128) int    g_es[MAXE];
__device__ __align__(128) int    g_ed[MAXE];
__device__ __align__(128) int    g_rank[MAXE];
__device__ __align__(128) __half g_hA[(size_t)MAXN * DH];   // fp16 gathered features
__device__ __align__(128) float  g_bufB[(size_t)MAXN * DH]; // fp32 conv output
__device__ __align__(128) __half g_hgf[(size_t)MAXN * NC];  // fp16 final-layer features
__device__ volatile ull g_lk[MAXBLKS];   // decoupled-lookback: (sum<<2)|flag
__device__ float g_statsA[DH + 1];
__device__ float g_statsB[DH + 1];
__device__ int   g_is64;

// ---------------- helpers ----------------
__device__ __forceinline__ void ffma2(ull& d, ull a, ull b) {
    asm("fma.rn.f32x2 %0, %1, %2, %0;" : "+l"(d) : "l"(a), "l"(b));
}
__device__ __forceinline__ ull splat2(float v) {
    unsigned u = __float_as_uint(v);
    ull r;
    asm("mov.b64 %0, {%1,%1};" : "=l"(r) : "r"(u));
    return r;
}
__device__ __forceinline__ float4 h4_to_f4(uint2 u) {
    __half2 h0 = *reinterpret_cast<__half2*>(&u.x);
    __half2 h1 = *reinterpret_cast<__half2*>(&u.y);
    float2 f0 = __half22float2(h0);
    float2 f1 = __half22float2(h1);
    return make_float4(f0.x, f0.y, f1.x, f1.y);
}

// ---------------- init: deg=0, statsA=0, lookback flags, detect dtype ----------------
__global__ void k_init(const int* __restrict__ p, int N) {
    int i = blockIdx.x * blockDim.x + threadIdx.x;
    if (i < N) g_deg[i] = 0;
    if (blockIdx.x == 0) {
        int tid = threadIdx.x;
        if (tid < DH + 1) g_statsA[tid] = 0.f;
        if (tid < MAXBLKS) g_lk[tid] = 0ull;
        if (tid < 32) {
            int v = p[2 * tid + 1];
            unsigned any = __ballot_sync(0xffffffffu, v != 0);
            if (tid == 0) g_is64 = (any == 0) ? 1 : 0;
        }
    }
}

// ------- count degrees + per-edge rank + cache int32 edges (2 edges/thread) ----------
__global__ void k_count(const void* __restrict__ ei, int E) {
    int idx = blockIdx.x * blockDim.x + threadIdx.x;
    int e = idx * 2;
    if (e >= E) return;
    int s0, s1 = 0, d0, d1 = 0;
    bool pair = (e + 1 < E);
    int is64 = g_is64;
    if (is64) {
        const long long* ps = (const long long*)ei;
        const long long* pd = ps + E;
        if ((E & 1) == 0) {
            longlong2 sv = *(const longlong2*)(ps + e);
            longlong2 dv = *(const longlong2*)(pd + e);
            s0 = (int)sv.x; s1 = (int)sv.y;
            d0 = (int)dv.x; d1 = (int)dv.y;
        } else {
            s0 = (int)ps[e]; d0 = (int)pd[e];
            if (pair) { s1 = (int)ps[e + 1]; d1 = (int)pd[e + 1]; }
        }
    } else {
        const int* ps = (const int*)ei;
        const int* pd = ps + E;
        if ((E & 1) == 0) {
            int2 sv = *(const int2*)(ps + e);
            int2 dv = *(const int2*)(pd + e);
            s0 = sv.x; s1 = sv.y;
            d0 = dv.x; d1 = dv.y;
        } else {
            s0 = ps[e]; d0 = pd[e];
            if (pair) { s1 = ps[e + 1]; d1 = pd[e + 1]; }
        }
    }
    if (is64) g_es[e] = s0;      // int32 path: src already readable from ei in k_fill
    g_ed[e] = d0;
    g_rank[e] = atomicAdd(&g_deg[d0], 1);
    if (pair) {
        if (is64) g_es[e + 1] = s1;
        g_ed[e + 1] = d1;
        g_rank[e + 1] = atomicAdd(&g_deg[d1], 1);
    }
}

// ---------------- fused scan (decoupled lookback): row_ptr + dinv ----------------
__global__ void k_scan(int N) {
    __shared__ int sm[256];
    __shared__ int s_pref;
    int blk = blockIdx.x, tid = threadIdx.x;
    int base = blk * SCAN_CHUNK + tid * 4;
    int d[4];
    int s = 0;
#pragma unroll
    for (int j = 0; j < 4; j++) {
        int i = base + j;
        d[j] = (i < N) ? g_deg[i] : 0;
        s += d[j];
    }
    sm[tid] = s;
    __syncthreads();
    int own = s;
    for (int off = 1; off < 256; off <<= 1) {
        int add = (tid >= off) ? sm[tid - off] : 0;
        __syncthreads();
        sm[tid] += add;
        __syncthreads();
    }
    int incl = sm[tid];
    int total = sm[255];

    if (tid == 0) {
        if (blk == 0) {
            g_lk[0] = ((ull)(unsigned)total << 2) | 2ull;
            s_pref = 0;
        } else {
            g_lk[blk] = ((ull)(unsigned)total << 2) | 1ull;
            int run = 0;
            int pb = blk - 1;
            while (true) {
                ull w;
                do { w = g_lk[pb]; } while ((w & 3ull) == 0ull);
                run += (int)(w >> 2);
                if ((w & 3ull) == 2ull) break;
                pb--;
            }
            s_pref = run;
            g_lk[blk] = ((ull)(unsigned)(run + total) << 2) | 2ull;
        }
    }
    __syncthreads();

    int excl = incl - own + s_pref;
#pragma unroll
    for (int j = 0; j < 4; j++) {
        int i = base + j;
        if (i < N) {
            g_rp[i] = excl;
            g_dinv[i] = rsqrtf((float)(d[j] + 1));
            if (i == N - 1) g_rp[N] = excl + d[j];
            excl += d[j];
        }
    }
}

// ---------------- fill: atomic-free (rank precomputed in k_count) ----------------
__global__ void k_fill(const void* __restrict__ ei, int E) {
    int e = blockIdx.x * blockDim.x + threadIdx.x;
    if (e < E) {
        int dst = g_ed[e];
        int r = g_rank[e];
        int src = g_is64 ? g_es[e] : ((const int*)ei)[e];
        g_csr[g_rp[dst] + r] = src;
    }
}

// ---------------- layer-0 GEMM: g_hA = fp16( dinv ⊙ (x @ W0) ) ----------------
__global__ void __launch_bounds__(128) k_gemm0(const float* __restrict__ x,
                                               const float* __restrict__ W, int N) {
    __shared__ float xs[BK * XS_ROW];
    __shared__ ull   ws2[BK * WS_ROW];
    int tid = threadIdx.x;
    int ty = tid >> 2;
    int tx = tid & 3;
    int rowBase = blockIdx.x * BM;

    if (blockIdx.x == 0 && tid < DH + 1) g_statsB[tid] = 0.f;

    ull acc2[4][8];
#pragma unroll
    for (int ip = 0; ip < 4; ip++)
#pragma unroll
        for (int j = 0; j < 8; j++) acc2[ip][j] = 0ull;

    float4 pre[8];
#pragma unroll
    for (int i = 0; i < 8; i++) {
        int idx = tid + i * 128;
        int row = idx >> 2;
        int kq = (idx & 3) << 2;
        int gr = rowBase + row;
        pre[i] = (gr < N) ? *(const float4*)(x + (size_t)gr * D_IN + kq)
                          : make_float4(0.f, 0.f, 0.f, 0.f);
    }

    for (int k0 = 0; k0 < D_IN; k0 += BK) {
#pragma unroll
        for (int i = 0; i < 8; i++) {
            int idx = tid + i * 128;
            int row = idx >> 2;
            int kq = (idx & 3) << 2;
            int base = (row >> 3) * XS_G + (row & 7);
            xs[(kq + 0) * XS_ROW + base] = pre[i].x;
            xs[(kq + 1) * XS_ROW + base] = pre[i].y;
            xs[(kq + 2) * XS_ROW + base] = pre[i].z;
            xs[(kq + 3) * XS_ROW + base] = pre[i].w;
        }
        {
            int kk = tid >> 3;
            int nq = (tid & 7) << 2;
            float4 wv = *(const float4*)(W + (size_t)(k0 + kk) * DH + nq);
            int pbase = kk * WS_ROW + (nq >> 3) * WS_T + (nq & 7);
            ws2[pbase + 0] = splat2(wv.x);
            ws2[pbase + 1] = splat2(wv.y);
            ws2[pbase + 2] = splat2(wv.z);
            ws2[pbase + 3] = splat2(wv.w);
        }
        __syncthreads();

        if (k0 + BK < D_IN) {
#pragma unroll
            for (int i = 0; i < 8; i++) {
                int idx = tid + i * 128;
                int row = idx >> 2;
                int kq = (idx & 3) << 2;
                int gr = rowBase + row;
                pre[i] = (gr < N) ? *(const float4*)(x + (size_t)gr * D_IN + k0 + BK + kq)
                                  : make_float4(0.f, 0.f, 0.f, 0.f);
            }
        }

#pragma unroll
        for (int kk = 0; kk < BK; kk++) {
            const ull* ar = (const ull*)(xs + kk * XS_ROW + ty * XS_G);
            ull ap0 = ar[0], ap1 = ar[1], ap2 = ar[2], ap3 = ar[3];
            const ull* wr = ws2 + kk * WS_ROW + tx * WS_T;
#pragma unroll
            for (int j = 0; j < 8; j++) {
                ull bs = wr[j];
                ffma2(acc2[0][j], ap0, bs);
                ffma2(acc2[1][j], ap1, bs);
                ffma2(acc2[2][j], ap2, bs);
                ffma2(acc2[3][j], ap3, bs);
            }
        }
        __syncthreads();
    }

#pragma unroll
    for (int ip = 0; ip < 4; ip++) {
        int r0 = rowBase + ty * 8 + 2 * ip;
        int r1 = r0 + 1;
        float dv0 = (r0 < N) ? g_dinv[r0] : 0.f;
        float dv1 = (r1 < N) ? g_dinv[r1] : 0.f;
        float v0[8], v1[8];
#pragma unroll
        for (int j = 0; j < 8; j++) {
            ull v = acc2[ip][j];
            v0[j] = __uint_as_float((unsigned)v) * dv0;
            v1[j] = __uint_as_float((unsigned)(v >> 32)) * dv1;
        }
#pragma unroll
        for (int j2 = 0; j2 < 4; j2++) {
            if (r0 < N)
                *(__half2*)(g_hA + (size_t)r0 * DH + tx * 8 + 2 * j2) =
                    __floats2half2_rn(v0[2 * j2], v0[2 * j2 + 1]);
            if (r1 < N)
                *(__half2*)(g_hA + (size_t)r1 * DH + tx * 8 + 2 * j2) =
                    __floats2half2_rn(v1[2 * j2], v1[2 * j2 + 1]);
        }
    }
}

// ---- propagation D=32 fp16 gather (4 nodes/warp) + fused pairnorm stats ----
__global__ void k_prop32(const float* __restrict__ b, int N, int which) {
    __shared__ float s_cs[DH];
    __shared__ float s_ss;
    int tid = threadIdx.x;
    if (tid < DH) s_cs[tid] = 0.f;
    if (tid == DH) s_ss = 0.f;
    __syncthreads();

    int lane = tid & 31;
    int l8 = lane & 7;
    int g8 = lane >> 3;
    int gwarp = (blockIdx.x * blockDim.x + tid) >> 5;
    int w = gwarp * 4 + g8;
    bool alive = (w < N);
    int wc = alive ? w : 0;

    float4 acc = h4_to_f4(*((const uint2*)(g_hA + (size_t)wc * DH) + l8));  // self loop
    int beg = g_rp[wc];
    int deg = g_rp[wc + 1] - beg;
    if (!alive) deg = 0;

    int mx = deg;
    mx = max(mx, __shfl_xor_sync(0xffffffffu, mx, 16));
    mx = max(mx, __shfl_xor_sync(0xffffffffu, mx, 8));

    for (int t0 = 0; t0 < mx; t0 += 8) {
        int n = deg - t0;
        int s = (l8 < n) ? g_csr[beg + t0 + l8] : 0;
#pragma unroll
        for (int k = 0; k < 8; k++) {
            int sk = __shfl_sync(0xffffffffu, s, k, 8);
            if (k < n) {
                float4 v = h4_to_f4(*((const uint2*)(g_hA + (size_t)sk * DH) + l8));
                acc.x += v.x; acc.y += v.y; acc.z += v.z; acc.w += v.w;
            }
        }
    }

    float4 o = make_float4(0.f, 0.f, 0.f, 0.f);
    if (alive) {
        float dv = g_dinv[w];
        float4 bb = *(const float4*)(b + l8 * 4);
        o.x = dv * acc.x + bb.x;
        o.y = dv * acc.y + bb.y;
        o.z = dv * acc.z + bb.z;
        o.w = dv * acc.w + bb.w;
        *(float4*)(g_bufB + (size_t)w * DH + l8 * 4) = o;
    }

    float ssl = o.x * o.x + o.y * o.y + o.z * o.z + o.w * o.w;
#pragma unroll
    for (int off = 16; off; off >>= 1) ssl += __shfl_xor_sync(0xffffffffu, ssl, off);

    o.x += __shfl_xor_sync(0xffffffffu, o.x, 8);
    o.y += __shfl_xor_sync(0xffffffffu, o.y, 8);
    o.z += __shfl_xor_sync(0xffffffffu, o.z, 8);
    o.w += __shfl_xor_sync(0xffffffffu, o.w, 8);
    o.x += __shfl_xor_sync(0xffffffffu, o.x, 16);
    o.y += __shfl_xor_sync(0xffffffffu, o.y, 16);
    o.z += __shfl_xor_sync(0xffffffffu, o.z, 16);
    o.w += __shfl_xor_sync(0xffffffffu, o.w, 16);
    if (lane < 8) {
        atomicAdd(&s_cs[l8 * 4 + 0], o.x);
        atomicAdd(&s_cs[l8 * 4 + 1], o.y);
        atomicAdd(&s_cs[l8 * 4 + 2], o.z);
        atomicAdd(&s_cs[l8 * 4 + 3], o.w);
    }
    if (lane == 0) atomicAdd(&s_ss, ssl);
    __syncthreads();

    float* st = which ? g_statsB : g_statsA;
    if (tid < DH) atomicAdd(&st[tid], s_cs[tid]);
    if (tid == DH) atomicAdd(&st[DH], s_ss);
}

// ---- fused pairnorm + relu + (t @ W1) + dinv scale: bufB -> g_hA (stats A) ----
__global__ void k_transform(const float* __restrict__ Wmat, int N, float invN) {
    __shared__ float ws[DH * DH];
    int tid = threadIdx.x, lane = tid & 31;
    for (int i = tid; i < DH * DH; i += blockDim.x) ws[i] = Wmat[i];
    __syncthreads();

    float mu = g_statsA[lane] * invN;
    float m2 = mu * mu;
#pragma unroll
    for (int off = 16; off; off >>= 1) m2 += __shfl_xor_sync(0xffffffffu, m2, off);
    float scale = rsqrtf(1e-5f + g_statsA[DH] * invN - m2);

    int warp0 = (blockIdx.x * blockDim.x + tid) >> 5;
    int nw = (gridDim.x * blockDim.x) >> 5;
    for (int n = warp0; n < N; n += nw) {
        float t = (g_bufB[(size_t)n * DH + lane] - mu) * scale;
        t = fmaxf(t, 0.f);
        float acc = 0.f;
#pragma unroll
        for (int j = 0; j < DH; j++) {
            float tj = __shfl_sync(0xffffffffu, t, j);
            acc = fmaf(tj, ws[j * DH + lane], acc);
        }
        float val = acc * g_dinv[n];
        float vhi = __shfl_down_sync(0xffffffffu, val, 1);
        if ((lane & 1) == 0)
            *(__half2*)(g_hA + (size_t)n * DH + lane) = __floats2half2_rn(val, vhi);
    }
}

// ---- fused pairnorm + relu + (t @ Wf) + dinv scale: bufB -> g_hgf (stats B) ----
__global__ void k_transformF(const float* __restrict__ Wmat, int N, float invN) {
    __shared__ float ws[DH * NC];
    int tid = threadIdx.x, lane = tid & 31;
    for (int i = tid; i < DH * NC; i += blockDim.x) ws[i] = Wmat[i];
    __syncthreads();

    float mu = g_statsB[lane] * invN;
    float m2 = mu * mu;
#pragma unroll
    for (int off = 16; off; off >>= 1) m2 += __shfl_xor_sync(0xffffffffu, m2, off);
    float scale = rsqrtf(1e-5f + g_statsB[DH] * invN - m2);

    int warp0 = (blockIdx.x * blockDim.x + tid) >> 5;
    int nw = (gridDim.x * blockDim.x) >> 5;
    int l8 = lane & 7;
    for (int n = warp0; n < N; n += nw) {
        float t = (g_bufB[(size_t)n * DH + lane] - mu) * scale;
        t = fmaxf(t, 0.f);
        float acc0 = 0.f, acc1 = 0.f;
#pragma unroll
        for (int j = 0; j < DH; j++) {
            float tj = __shfl_sync(0xffffffffu, t, j);
            acc0 = fmaf(tj, ws[j * NC + lane], acc0);
            acc1 = fmaf(tj, ws[j * NC + 32 + l8], acc1);
        }
        float dv = g_dinv[n];
        float v0 = acc0 * dv;
        float v0hi = __shfl_down_sync(0xffffffffu, v0, 1);
        if ((lane & 1) == 0)
            *(__half2*)(g_hgf + (size_t)n * NC + lane) = __floats2half2_rn(v0, v0hi);
        float v1 = acc1 * dv;
        float v1hi = __shfl_down_sync(0xffffffffu, v1, 1);
        if (lane < 8 && (lane & 1) == 0)
            *(__half2*)(g_hgf + (size_t)n * NC + 32 + lane) = __floats2half2_rn(v1, v1hi);
    }
}

// ---------------- final propagation D=40 fp16 gather (4 nodes/warp) -> d_out ----------
__global__ void k_propF(const float* __restrict__ bf, float* __restrict__ out, int N) {
    int tid = threadIdx.x;
    int lane = tid & 31;
    int l8 = lane & 7;
    int g8 = lane >> 3;
    int gwarp = (blockIdx.x * blockDim.x + tid) >> 5;
    int w = gwarp * 4 + g8;
    bool alive = (w < N);
    int wc = alive ? w : 0;

    const __half* srow = g_hgf + (size_t)wc * NC;
    float4 acc = h4_to_f4(*((const uint2*)srow + l8));
    float2 acc1 = make_float2(0.f, 0.f);
    if (l8 < 4) {
        unsigned u = *(const unsigned*)(srow + 32 + l8 * 2);
        acc1 = __half22float2(*reinterpret_cast<__half2*>(&u));
    }
    int beg = g_rp[wc];
    int deg = g_rp[wc + 1] - beg;
    if (!alive) deg = 0;

    int mx = deg;
    mx = max(mx, __shfl_xor_sync(0xffffffffu, mx, 16));
    mx = max(mx, __shfl_xor_sync(0xffffffffu, mx, 8));

    for (int t0 = 0; t0 < mx; t0 += 8) {
        int n = deg - t0;
        int s = (l8 < n) ? g_csr[beg + t0 + l8] : 0;
#pragma unroll
        for (int k = 0; k < 8; k++) {
            int sk = __shfl_sync(0xffffffffu, s, k, 8);
            if (k < n) {
                const __half* row = g_hgf + (size_t)sk * NC;
                float4 v = h4_to_f4(*((const uint2*)row + l8));
                acc.x += v.x; acc.y += v.y; acc.z += v.z; acc.w += v.w;
                if (l8 < 4) {
                    unsigned u = *(const unsigned*)(row + 32 + l8 * 2);
                    float2 v1 = __half22float2(*reinterpret_cast<__half2*>(&u));
                    acc1.x += v1.x; acc1.y += v1.y;
                }
            }
        }
    }
    if (alive) {
        float dv = g_dinv[w];
        float4 bb = *(const float4*)(bf + l8 * 4);
        float4 o;
        o.x = dv * acc.x + bb.x;
        o.y = dv * acc.y + bb.y;
        o.z = dv * acc.z + bb.z;
        o.w = dv * acc.w + bb.w;
        *(float4*)(out + (size_t)w * NC + l8 * 4) = o;
        if (l8 < 4) {
            float2 be = *(const float2*)(bf + 32 + l8 * 2);
            float2 o1;
            o1.x = dv * acc1.x + be.x;
            o1.y = dv * acc1.y + be.y;
            *(float2*)(out + (size_t)w * NC + 32 + l8 * 2) = o1;
        }
    }
}

// ---------------- host launcher ----------------
extern "C" void kernel_launch(void* const* d_in, const int* in_sizes, int n_in,
                              void* d_out, int out_size) {
    const float* x  = (const float*)d_in[0];
    const void*  ei = d_in[1];
    const float* W0 = (const float*)d_in[2];
    const float* b0 = (const float*)d_in[3];
    const float* W1 = (const float*)d_in[4];
    const float* b1 = (const float*)d_in[5];
    const float* Wf = (const float*)d_in[6];
    const float* bf = (const float*)d_in[7];
    float* out = (float*)d_out;

    int N = in_sizes[0] / D_IN;
    int E = in_sizes[1] / 2;
    float invN = 1.f / (float)N;
    int NB = (N + SCAN_CHUNK - 1) / SCAN_CHUNK;
    int propBlocks = (N + 31) / 32;

    k_init<<<(N + 255) / 256, 256>>>((const int*)ei, N);                 // #1
    k_count<<<(E / 2 + 256) / 256, 256>>>(ei, E);                        // #2
    k_scan<<<NB, 256>>>(N);                                              // #3
    k_fill<<<(E + 255) / 256, 256>>>(ei, E);                             // #4 (profiled)

    k_gemm0<<<(N + BM - 1) / BM, 128>>>(x, W0, N);                       // #5
    k_prop32<<<propBlocks, 256>>>(b0, N, 0);                             // #6
    k_transform<<<592, 256>>>(W1, N, invN);                              // #7
    k_prop32<<<propBlocks, 256>>>(b1, N, 1);                             // #8
    k_transformF<<<592, 256>>>(Wf, N, invN);                             // #9
    k_propF<<<propBlocks, 256>>>(bf, out, N);                            // #10
}

// round 11
// speedup vs baseline: 1.0720x; 1.0459x over previous
#include <cuda_runtime.h>
#include <cuda_fp16.h>
#include <cstdint>
#include <cstddef>

#define D_IN 512
#define DH   32
#define NC   40
#define MAXN 100000
#define MAXE 3200000
#define SCAN_CHUNK 1024
#define MAXBLKS 128
#define BM 256
#define BK 16

// padded smem geometry (conflict-free)
#define XS_G   12
#define XS_ROW (32 * XS_G)
#define WS_T   10
#define WS_ROW (4 * WS_T)

typedef unsigned long long ull;

// ---------------- device scratch (referenced only from device code) ----------------
// NOTE on cross-replay state: g_deg and g_lk are zeroed by k_propF's tail each
// invocation (and are zero-initialized at module load), so every replay starts clean.
__device__ __align__(128) int      g_deg[MAXN];
__device__ __align__(128) int      g_rp[MAXN + 1];
__device__ __align__(128) float    g_dinv[MAXN];
__device__ __align__(128) int      g_csr[MAXE];
__device__ __align__(128) int      g_es[MAXE];
__device__ __align__(128) unsigned g_edrank[MAXE];   // dst | (rank<<17)
__device__ __align__(128) __half   g_hA[(size_t)MAXN * DH];
__device__ __align__(128) float    g_bufB[(size_t)MAXN * DH];
__device__ __align__(128) __half   g_hgf[(size_t)MAXN * NC];
__device__ volatile ull g_lk[MAXBLKS];
__device__ float g_statsA[DH + 1];
__device__ float g_statsB[DH + 1];

// ---------------- helpers ----------------
__device__ __forceinline__ void ffma2(ull& d, ull a, ull b) {
    asm("fma.rn.f32x2 %0, %1, %2, %0;" : "+l"(d) : "l"(a), "l"(b));
}
__device__ __forceinline__ ull splat2(float v) {
    unsigned u = __float_as_uint(v);
    ull r;
    asm("mov.b64 %0, {%1,%1};" : "=l"(r) : "r"(u));
    return r;
}
__device__ __forceinline__ float4 h4_to_f4(uint2 u) {
    __half2 h0 = *reinterpret_cast<__half2*>(&u.x);
    __half2 h1 = *reinterpret_cast<__half2*>(&u.y);
    float2 f0 = __half22float2(h0);
    float2 f1 = __half22float2(h1);
    return make_float4(f0.x, f0.y, f1.x, f1.y);
}

// per-block edge-dtype detection: int64 little-endian ids < 2^31 -> odd words all 0
__device__ __forceinline__ int detect_is64(const int* p, int tid, int* s_flag) {
    if (tid < 32) {
        int v = p[2 * tid + 1];
        unsigned any = __ballot_sync(0xffffffffu, v != 0);
        if (tid == 0) *s_flag = (any == 0) ? 1 : 0;
    }
    __syncthreads();
    return *s_flag;
}

// ------- #1 count: degrees + per-edge (dst,rank) pack + cache int32 src (int64 path) ---
__global__ void k_count(const void* __restrict__ ei, int E) {
    __shared__ int s_is64;
    int tid = threadIdx.x;
    int is64 = detect_is64((const int*)ei, tid, &s_is64);

    int e = (blockIdx.x * blockDim.x + tid) * 2;
    if (e >= E) return;
    int s0, s1 = 0, d0, d1 = 0;
    bool pair = (e + 1 < E);
    if (is64) {
        const long long* ps = (const long long*)ei;
        const long long* pd = ps + E;
        if ((E & 1) == 0) {
            longlong2 sv = *(const longlong2*)(ps + e);
            longlong2 dv = *(const longlong2*)(pd + e);
            s0 = (int)sv.x; s1 = (int)sv.y;
            d0 = (int)dv.x; d1 = (int)dv.y;
        } else {
            s0 = (int)ps[e]; d0 = (int)pd[e];
            if (pair) { s1 = (int)ps[e + 1]; d1 = (int)pd[e + 1]; }
        }
    } else {
        const int* ps = (const int*)ei;
        const int* pd = ps + E;
        if ((E & 1) == 0) {
            int2 sv = *(const int2*)(ps + e);
            int2 dv = *(const int2*)(pd + e);
            s0 = sv.x; s1 = sv.y;
            d0 = dv.x; d1 = dv.y;
        } else {
            s0 = ps[e]; d0 = pd[e];
            if (pair) { s1 = ps[e + 1]; d1 = pd[e + 1]; }
        }
    }
    if (is64) g_es[e] = s0;
    int r0 = atomicAdd(&g_deg[d0], 1);
    g_edrank[e] = (unsigned)d0 | ((unsigned)r0 << 17);
    if (pair) {
        if (is64) g_es[e + 1] = s1;
        int r1 = atomicAdd(&g_deg[d1], 1);
        g_edrank[e + 1] = (unsigned)d1 | ((unsigned)r1 << 17);
    }
}

// ------- #2 fused scan (decoupled lookback): row_ptr + dinv; block 0 zeroes statsA ------
__global__ void k_scan(int N) {
    __shared__ int sm[256];
    __shared__ int s_pref;
    int blk = blockIdx.x, tid = threadIdx.x;
    if (blk == 0 && tid < DH + 1) g_statsA[tid] = 0.f;
    int base = blk * SCAN_CHUNK + tid * 4;
    int d[4];
    int s = 0;
#pragma unroll
    for (int j = 0; j < 4; j++) {
        int i = base + j;
        d[j] = (i < N) ? g_deg[i] : 0;
        s += d[j];
    }
    sm[tid] = s;
    __syncthreads();
    int own = s;
    for (int off = 1; off < 256; off <<= 1) {
        int add = (tid >= off) ? sm[tid - off] : 0;
        __syncthreads();
        sm[tid] += add;
        __syncthreads();
    }
    int incl = sm[tid];
    int total = sm[255];

    if (tid == 0) {
        if (blk == 0) {
            g_lk[0] = ((ull)(unsigned)total << 2) | 2ull;
            s_pref = 0;
        } else {
            g_lk[blk] = ((ull)(unsigned)total << 2) | 1ull;
            int run = 0;
            int pb = blk - 1;
            while (true) {
                ull w;
                do { w = g_lk[pb]; } while ((w & 3ull) == 0ull);
                run += (int)(w >> 2);
                if ((w & 3ull) == 2ull) break;
                pb--;
            }
            s_pref = run;
            g_lk[blk] = ((ull)(unsigned)(run + total) << 2) | 2ull;
        }
    }
    __syncthreads();

    int excl = incl - own + s_pref;
#pragma unroll
    for (int j = 0; j < 4; j++) {
        int i = base + j;
        if (i < N) {
            g_rp[i] = excl;
            g_dinv[i] = rsqrtf((float)(d[j] + 1));
            if (i == N - 1) g_rp[N] = excl + d[j];
            excl += d[j];
        }
    }
}

// ------- #3 FUSED: blocks [0,GB) = layer-0 GEMM, blocks [GB,..) = CSR fill ----------
__global__ void __launch_bounds__(128) k_fillgemm(const float* __restrict__ x,
                                                  const float* __restrict__ W,
                                                  const void* __restrict__ ei,
                                                  int N, int E, int GB) {
    if ((int)blockIdx.x >= GB) {
        // ---------- fill branch: atomic-free scatter ----------
        __shared__ int s_is64;
        int tid = threadIdx.x;
        int is64 = detect_is64((const int*)ei, tid, &s_is64);
        int base = (blockIdx.x - GB) * 512 + tid;
#pragma unroll
        for (int k = 0; k < 4; k++) {
            int e = base + k * 128;
            if (e < E) {
                unsigned wrd = g_edrank[e];
                int dst = (int)(wrd & 0x1FFFFu);
                int r = (int)(wrd >> 17);
                int src = is64 ? g_es[e] : ((const int*)ei)[e];
                g_csr[g_rp[dst] + r] = src;
            }
        }
        return;
    }

    // ---------- GEMM branch: g_hA = fp16( dinv ⊙ (x @ W0) ) ----------
    __shared__ float xs[BK * XS_ROW];
    __shared__ ull   ws2[BK * WS_ROW];
    int tid = threadIdx.x;
    int ty = tid >> 2;
    int tx = tid & 3;
    int rowBase = blockIdx.x * BM;

    if (blockIdx.x == 0 && tid < DH + 1) g_statsB[tid] = 0.f;

    ull acc2[4][8];
#pragma unroll
    for (int ip = 0; ip < 4; ip++)
#pragma unroll
        for (int j = 0; j < 8; j++) acc2[ip][j] = 0ull;

    float4 pre[8];
#pragma unroll
    for (int i = 0; i < 8; i++) {
        int idx = tid + i * 128;
        int row = idx >> 2;
        int kq = (idx & 3) << 2;
        int gr = rowBase + row;
        pre[i] = (gr < N) ? *(const float4*)(x + (size_t)gr * D_IN + kq)
                          : make_float4(0.f, 0.f, 0.f, 0.f);
    }

    for (int k0 = 0; k0 < D_IN; k0 += BK) {
#pragma unroll
        for (int i = 0; i < 8; i++) {
            int idx = tid + i * 128;
            int row = idx >> 2;
            int kq = (idx & 3) << 2;
            int base = (row >> 3) * XS_G + (row & 7);
            xs[(kq + 0) * XS_ROW + base] = pre[i].x;
            xs[(kq + 1) * XS_ROW + base] = pre[i].y;
            xs[(kq + 2) * XS_ROW + base] = pre[i].z;
            xs[(kq + 3) * XS_ROW + base] = pre[i].w;
        }
        {
            int kk = tid >> 3;
            int nq = (tid & 7) << 2;
            float4 wv = *(const float4*)(W + (size_t)(k0 + kk) * DH + nq);
            int pbase = kk * WS_ROW + (nq >> 3) * WS_T + (nq & 7);
            ws2[pbase + 0] = splat2(wv.x);
            ws2[pbase + 1] = splat2(wv.y);
            ws2[pbase + 2] = splat2(wv.z);
            ws2[pbase + 3] = splat2(wv.w);
        }
        __syncthreads();

        if (k0 + BK < D_IN) {
#pragma unroll
            for (int i = 0; i < 8; i++) {
                int idx = tid + i * 128;
                int row = idx >> 2;
                int kq = (idx & 3) << 2;
                int gr = rowBase + row;
                pre[i] = (gr < N) ? *(const float4*)(x + (size_t)gr * D_IN + k0 + BK + kq)
                                  : make_float4(0.f, 0.f, 0.f, 0.f);
            }
        }

#pragma unroll
        for (int kk = 0; kk < BK; kk++) {
            const ull* ar = (const ull*)(xs + kk * XS_ROW + ty * XS_G);
            ull ap0 = ar[0], ap1 = ar[1], ap2 = ar[2], ap3 = ar[3];
            const ull* wr = ws2 + kk * WS_ROW + tx * WS_T;
#pragma unroll
            for (int j = 0; j < 8; j++) {
                ull bs = wr[j];
                ffma2(acc2[0][j], ap0, bs);
                ffma2(acc2[1][j], ap1, bs);
                ffma2(acc2[2][j], ap2, bs);
                ffma2(acc2[3][j], ap3, bs);
            }
        }
        __syncthreads();
    }

#pragma unroll
    for (int ip = 0; ip < 4; ip++) {
        int r0 = rowBase + ty * 8 + 2 * ip;
        int r1 = r0 + 1;
        float dv0 = (r0 < N) ? g_dinv[r0] : 0.f;
        float dv1 = (r1 < N) ? g_dinv[r1] : 0.f;
        float v0[8], v1[8];
#pragma unroll
        for (int j = 0; j < 8; j++) {
            ull v = acc2[ip][j];
            v0[j] = __uint_as_float((unsigned)v) * dv0;
            v1[j] = __uint_as_float((unsigned)(v >> 32)) * dv1;
        }
#pragma unroll
        for (int j2 = 0; j2 < 4; j2++) {
            if (r0 < N)
                *(__half2*)(g_hA + (size_t)r0 * DH + tx * 8 + 2 * j2) =
                    __floats2half2_rn(v0[2 * j2], v0[2 * j2 + 1]);
            if (r1 < N)
                *(__half2*)(g_hA + (size_t)r1 * DH + tx * 8 + 2 * j2) =
                    __floats2half2_rn(v1[2 * j2], v1[2 * j2 + 1]);
        }
    }
}

// ---- #4/#6 propagation D=32 fp16 gather (4 nodes/warp) + fused pairnorm stats ----
__global__ void k_prop32(const float* __restrict__ b, int N, int which) {
    __shared__ float s_cs[DH];
    __shared__ float s_ss;
    int tid = threadIdx.x;
    if (tid < DH) s_cs[tid] = 0.f;
    if (tid == DH) s_ss = 0.f;
    __syncthreads();

    int lane = tid & 31;
    int l8 = lane & 7;
    int g8 = lane >> 3;
    int gwarp = (blockIdx.x * blockDim.x + tid) >> 5;
    int w = gwarp * 4 + g8;
    bool alive = (w < N);
    int wc = alive ? w : 0;

    float4 acc = h4_to_f4(*((const uint2*)(g_hA + (size_t)wc * DH) + l8));  // self loop
    int beg = g_rp[wc];
    int deg = g_rp[wc + 1] - beg;
    if (!alive) deg = 0;

    int mx = deg;
    mx = max(mx, __shfl_xor_sync(0xffffffffu, mx, 16));
    mx = max(mx, __shfl_xor_sync(0xffffffffu, mx, 8));

    for (int t0 = 0; t0 < mx; t0 += 8) {
        int n = deg - t0;
        int s = (l8 < n) ? g_csr[beg + t0 + l8] : 0;
#pragma unroll
        for (int k = 0; k < 8; k++) {
            int sk = __shfl_sync(0xffffffffu, s, k, 8);
            if (k < n) {
                float4 v = h4_to_f4(*((const uint2*)(g_hA + (size_t)sk * DH) + l8));
                acc.x += v.x; acc.y += v.y; acc.z += v.z; acc.w += v.w;
            }
        }
    }

    float4 o = make_float4(0.f, 0.f, 0.f, 0.f);
    if (alive) {
        float dv = g_dinv[w];
        float4 bb = *(const float4*)(b + l8 * 4);
        o.x = dv * acc.x + bb.x;
        o.y = dv * acc.y + bb.y;
        o.z = dv * acc.z + bb.z;
        o.w = dv * acc.w + bb.w;
        *(float4*)(g_bufB + (size_t)w * DH + l8 * 4) = o;
    }

    float ssl = o.x * o.x + o.y * o.y + o.z * o.z + o.w * o.w;
#pragma unroll
    for (int off = 16; off; off >>= 1) ssl += __shfl_xor_sync(0xffffffffu, ssl, off);

    o.x += __shfl_xor_sync(0xffffffffu, o.x, 8);
    o.y += __shfl_xor_sync(0xffffffffu, o.y, 8);
    o.z += __shfl_xor_sync(0xffffffffu, o.z, 8);
    o.w += __shfl_xor_sync(0xffffffffu, o.w, 8);
    o.x += __shfl_xor_sync(0xffffffffu, o.x, 16);
    o.y += __shfl_xor_sync(0xffffffffu, o.y, 16);
    o.z += __shfl_xor_sync(0xffffffffu, o.z, 16);
    o.w += __shfl_xor_sync(0xffffffffu, o.w, 16);
    if (lane < 8) {
        atomicAdd(&s_cs[l8 * 4 + 0], o.x);
        atomicAdd(&s_cs[l8 * 4 + 1], o.y);
        atomicAdd(&s_cs[l8 * 4 + 2], o.z);
        atomicAdd(&s_cs[l8 * 4 + 3], o.w);
    }
    if (lane == 0) atomicAdd(&s_ss, ssl);
    __syncthreads();

    float* st = which ? g_statsB : g_statsA;
    if (tid < DH) atomicAdd(&st[tid], s_cs[tid]);
    if (tid == DH) atomicAdd(&st[DH], s_ss);
}

// ---- #5 fused pairnorm + relu + (t @ W1) + dinv scale: bufB -> g_hA (stats A) ----
__global__ void k_transform(const float* __restrict__ Wmat, int N, float invN) {
    __shared__ float ws[DH * DH];
    int tid = threadIdx.x, lane = tid & 31;
    for (int i = tid; i < DH * DH; i += blockDim.x) ws[i] = Wmat[i];
    __syncthreads();

    float mu = g_statsA[lane] * invN;
    float m2 = mu * mu;
#pragma unroll
    for (int off = 16; off; off >>= 1) m2 += __shfl_xor_sync(0xffffffffu, m2, off);
    float scale = rsqrtf(1e-5f + g_statsA[DH] * invN - m2);

    int warp0 = (blockIdx.x * blockDim.x + tid) >> 5;
    int nw = (gridDim.x * blockDim.x) >> 5;
    for (int n = warp0; n < N; n += nw) {
        float t = (g_bufB[(size_t)n * DH + lane] - mu) * scale;
        t = fmaxf(t, 0.f);
        float acc = 0.f;
#pragma unroll
        for (int j = 0; j < DH; j++) {
            float tj = __shfl_sync(0xffffffffu, t, j);
            acc = fmaf(tj, ws[j * DH + lane], acc);
        }
        float val = acc * g_dinv[n];
        float vhi = __shfl_down_sync(0xffffffffu, val, 1);
        if ((lane & 1) == 0)
            *(__half2*)(g_hA + (size_t)n * DH + lane) = __floats2half2_rn(val, vhi);
    }
}

// ---- #7 fused pairnorm + relu + (t @ Wf) + dinv scale: bufB -> g_hgf (stats B) ----
__global__ void k_transformF(const float* __restrict__ Wmat, int N, float invN) {
    __shared__ float ws[DH * NC];
    int tid = threadIdx.x, lane = tid & 31;
    for (int i = tid; i < DH * NC; i += blockDim.x) ws[i] = Wmat[i];
    __syncthreads();

    float mu = g_statsB[lane] * invN;
    float m2 = mu * mu;
#pragma unroll
    for (int off = 16; off; off >>= 1) m2 += __shfl_xor_sync(0xffffffffu, m2, off);
    float scale = rsqrtf(1e-5f + g_statsB[DH] * invN - m2);

    int warp0 = (blockIdx.x * blockDim.x + tid) >> 5;
    int nw = (gridDim.x * blockDim.x) >> 5;
    int l8 = lane & 7;
    for (int n = warp0; n < N; n += nw) {
        float t = (g_bufB[(size_t)n * DH + lane] - mu) * scale;
        t = fmaxf(t, 0.f);
        float acc0 = 0.f, acc1 = 0.f;
#pragma unroll
        for (int j = 0; j < DH; j++) {
            float tj = __shfl_sync(0xffffffffu, t, j);
            acc0 = fmaf(tj, ws[j * NC + lane], acc0);
            acc1 = fmaf(tj, ws[j * NC + 32 + l8], acc1);
        }
        float dv = g_dinv[n];
        float v0 = acc0 * dv;
        float v0hi = __shfl_down_sync(0xffffffffu, v0, 1);
        if ((lane & 1) == 0)
            *(__half2*)(g_hgf + (size_t)n * NC + lane) = __floats2half2_rn(v0, v0hi);
        float v1 = acc1 * dv;
        float v1hi = __shfl_down_sync(0xffffffffu, v1, 1);
        if (lane < 8 && (lane & 1) == 0)
            *(__half2*)(g_hgf + (size_t)n * NC + 32 + lane) = __floats2half2_rn(v1, v1hi);
    }
}

// ---- #8 final propagation D=40 -> d_out; tail zeroes deg/lk for the next replay ----
__global__ void k_propF(const float* __restrict__ bf, float* __restrict__ out, int N) {
    int tid = threadIdx.x;
    // cleanup for next invocation (safe: deg/lk unused in this kernel)
    int gi = blockIdx.x * blockDim.x + tid;
    if (gi < N) g_deg[gi] = 0;
    if (gi < MAXBLKS) g_lk[gi] = 0ull;

    int lane = tid & 31;
    int l8 = lane & 7;
    int g8 = lane >> 3;
    int gwarp = gi >> 5;
    int w = gwarp * 4 + g8;
    bool alive = (w < N);
    int wc = alive ? w : 0;

    const __half* srow = g_hgf + (size_t)wc * NC;
    float4 acc = h4_to_f4(*((const uint2*)srow + l8));
    float2 acc1 = make_float2(0.f, 0.f);
    if (l8 < 4) {
        unsigned u = *(const unsigned*)(srow + 32 + l8 * 2);
        acc1 = __half22float2(*reinterpret_cast<__half2*>(&u));
    }
    int beg = g_rp[wc];
    int deg = g_rp[wc + 1] - beg;
    if (!alive) deg = 0;

    int mx = deg;
    mx = max(mx, __shfl_xor_sync(0xffffffffu, mx, 16));
    mx = max(mx, __shfl_xor_sync(0xffffffffu, mx, 8));

    for (int t0 = 0; t0 < mx; t0 += 8) {
        int n = deg - t0;
        int s = (l8 < n) ? g_csr[beg + t0 + l8] : 0;
#pragma unroll
        for (int k = 0; k < 8; k++) {
            int sk = __shfl_sync(0xffffffffu, s, k, 8);
            if (k < n) {
                const __half* row = g_hgf + (size_t)sk * NC;
                float4 v = h4_to_f4(*((const uint2*)row + l8));
                acc.x += v.x; acc.y += v.y; acc.z += v.z; acc.w += v.w;
                if (l8 < 4) {
                    unsigned u = *(const unsigned*)(row + 32 + l8 * 2);
                    float2 v1 = __half22float2(*reinterpret_cast<__half2*>(&u));
                    acc1.x += v1.x; acc1.y += v1.y;
                }
            }
        }
    }
    if (alive) {
        float dv = g_dinv[w];
        float4 bb = *(const float4*)(bf + l8 * 4);
        float4 o;
        o.x = dv * acc.x + bb.x;
        o.y = dv * acc.y + bb.y;
        o.z = dv * acc.z + bb.z;
        o.w = dv * acc.w + bb.w;
        *(float4*)(out + (size_t)w * NC + l8 * 4) = o;
        if (l8 < 4) {
            float2 be = *(const float2*)(bf + 32 + l8 * 2);
            float2 o1;
            o1.x = dv * acc1.x + be.x;
            o1.y = dv * acc1.y + be.y;
            *(float2*)(out + (size_t)w * NC + 32 + l8 * 2) = o1;
        }
    }
}

// ---------------- host launcher ----------------
extern "C" void kernel_launch(void* const* d_in, const int* in_sizes, int n_in,
                              void* d_out, int out_size) {
    const float* x  = (const float*)d_in[0];
    const void*  ei = d_in[1];
    const float* W0 = (const float*)d_in[2];
    const float* b0 = (const float*)d_in[3];
    const float* W1 = (const float*)d_in[4];
    const float* b1 = (const float*)d_in[5];
    const float* Wf = (const float*)d_in[6];
    const float* bf = (const float*)d_in[7];
    float* out = (float*)d_out;

    int N = in_sizes[0] / D_IN;
    int E = in_sizes[1] / 2;
    float invN = 1.f / (float)N;
    int NB = (N + SCAN_CHUNK - 1) / SCAN_CHUNK;
    int propBlocks = (N + 31) / 32;
    int GB = (N + BM - 1) / BM;          // gemm blocks
    int FB = (E + 511) / 512;            // fill blocks (128 thr x 4 edges)

    k_count<<<(E / 2 + 255) / 256, 256>>>(ei, E);                        // #1
    k_scan<<<NB, 256>>>(N);                                              // #2
    k_fillgemm<<<GB + FB, 128>>>(x, W0, ei, N, E, GB);                   // #3
    k_prop32<<<propBlocks, 256>>>(b0, N, 0);                             // #4 (profiled)
    k_transform<<<592, 256>>>(W1, N, invN);                              // #5
    k_prop32<<<propBlocks, 256>>>(b1, N, 1);                             // #6
    k_transformF<<<592, 256>>>(Wf, N, invN);                             // #7
    k_propF<<<propBlocks, 256>>>(bf, out, N);                            // #8
}